// round 16
// baseline (speedup 1.0000x reference)
#include <cuda_runtime.h>
#include <cuda_fp16.h>

// ForwardWarp: forward splatting with Gaussian softmax weights.
// img, counts: (8,1,720,1280) f32; flo: (8,2,720,1280) f32 (ch0 = y shifts W, ch1 = x shifts H)
// out: [0:S) = img_warp / (one_warp + eps), [S:2S) = one_warp
//
// TWO-copy scratch (keyed by column parity pc = iy1&1), halving normalize read+zero bytes
// vs the 4-copy R11 design. Copy pc stores cell (r, cc) at word (r+1)*RS + cc + pc:
//  - pixel's row tap = 2 adjacent cells = one 8B-aligned red.global.add.noftz.v2.f16x2
//    (iy1+pc is always even); 2 REDs/pixel (rows ix1, ix1+1) = 2 x 8B quanta = same splat
//    cost as R11's single v4 (quanta model validated R1/R2/R8).
//  - each slot receives exactly 2 adds (top-row-tap + bottom-row-tap pixels) -> one extra
//    fp16 rounding at partial sums <=~1 -> rel_err ~3.5-5e-4 (vs 2.84e-4 packing floor).
// Pad rows (-1, 720) and pad cols absorb all boundary taps -> branchless splat, no edge
// path. Pads are never read and never zeroed (dirty; harmless - validated R11/R15).
// Normalize: thread owns 16 cells of one row; copy0 words aligned exactly, copy1 words
// shifted +1 handled with one prologue block + tail word; zero-stores exactly the words
// consumed (word-disjoint across threads -> race-free, no memset node).

static constexpr int N_ = 8;
static constexpr int H_ = 720;
static constexpr int W_ = 1280;
static constexpr int S_ = N_ * H_ * W_;     // 7,372,800
static constexpr float EPS_ = 1e-6f;

static constexpr int CHUNKS_ = 4;           // 2 images per chunk
static constexpr int PC_ = S_ / CHUNKS_;    // 1,843,200 pixels per chunk

static constexpr int RS_ = 1284;            // words per row (covers words 0..1281; 16B mult)
static constexpr int NR_ = 722;             // rows per copy-image (pad row -1 at 0, 720 at 721)
static constexpr int CPW_ = NR_ * RS_;      // words per copy-image = 927,048
static constexpr int SCR_WORDS_ = 4 * CPW_; // 2 copies x 2 images = 14.8MB

__device__ __align__(16) unsigned int g_S[SCR_WORDS_];  // BSS zero; fused zero-stores restore

__device__ __forceinline__ void red_v2h2(unsigned int* p, unsigned int s0, unsigned int s1) {
    asm volatile("red.global.add.noftz.v2.f16x2 [%0], {%1, %2};"
                 :: "l"(p), "r"(s0), "r"(s1) : "memory");
}
__device__ __forceinline__ unsigned int pack_h2(float a, float b) {
    __half2 h = __float22half2_rn(make_float2(a, b));
    return *reinterpret_cast<unsigned int*>(&h);
}
__device__ __forceinline__ float2 unpack_h2(unsigned int u) {
    return __half22float2(*reinterpret_cast<__half2*>(&u));
}

__global__ void __launch_bounds__(256) splat_kernel(
    const float* __restrict__ img,
    const float* __restrict__ counts,
    const float* __restrict__ flo,
    int chunk)
{
    int idx = chunk * PC_ + blockIdx.x * blockDim.x + threadIdx.x;

    int w  = idx % W_;
    int hw = idx / W_;
    int h  = hw % H_;
    int n  = hw / H_;
    int ni = n & 1;                 // image within chunk

    int flo_base = ((n * 2) * H_ + h) * W_ + w;
    float y = __ldcs(flo + flo_base);
    float x = __ldcs(flo + flo_base + H_ * W_);

    float im = __ldcs(img + idx);
    float c  = __ldcs(counts + idx);

    float x1 = floorf(x);
    float y1 = floorf(y);
    float fx = x - x1;
    float fy = y - y1;
    float gx = fx - 1.0f;
    float gy = fy - 1.0f;

    float dx1 = fx * fx, dx2 = gx * gx;
    float dy1 = fy * fy, dy2 = gy * gy;

    float w11 = __expf(-(dx1 + dy1));   // row ix1, col iy1
    float w12 = __expf(-(dx1 + dy2));   // row ix1, col iy2
    float w21 = __expf(-(dx2 + dy1));   // row ix2, col iy1
    float w22 = __expf(-(dx2 + dy2));   // row ix2, col iy2
    float inv = 1.0f / (w11 + w12 + w21 + w22);
    float cinv = c * inv;

    int ix1 = (int)x1 + h;
    int iy1 = (int)y1 + w;

    // whole footprint outside padded grid?
    if (ix1 < -1 || ix1 > H_ - 1 || iy1 < -1 || iy1 > W_ - 1) return;

    int pc = iy1 & 1;               // (-1 & 1) == 1 -> word 0 (pad col)
    unsigned int* p = g_S + (pc * 2 + ni) * CPW_ + (ix1 + 1) * RS_ + iy1 + pc;

    // row ix1: cells (ix1, iy1), (ix1, iy1+1); row ix1+1 likewise, one RS_ below
    red_v2h2(p,       pack_h2(im * (w11 * cinv), w11 * cinv),
                      pack_h2(im * (w12 * cinv), w12 * cinv));
    red_v2h2(p + RS_, pack_h2(im * (w21 * cinv), w21 * cinv),
                      pack_h2(im * (w22 * cinv), w22 * cinv));
}

// Thread owns 16 cells [c0, c0+16) of row r, image ni.
// copy0: cell cc at word cc (4 aligned uint4, fully owned).
// copy1: cell cc at word cc+1 -> words [c0+1, c0+16]: prologue uint4 at c0 (words 1..3
// used; word c0 belongs to the left neighbor), 3 full uint4, tail word c0+16.
// Zero-stores exactly the consumed words (disjoint) -> race-free. Pads never zeroed.
__global__ void __launch_bounds__(256) normalize_kernel(float* __restrict__ out, int chunk)
{
    int t = blockIdx.x * blockDim.x + threadIdx.x;  // 0 .. 115199 per chunk
    int cg   = t % (W_ / 16);       // 0..79 column group
    int rest = t / (W_ / 16);
    int r    = rest % H_;           // 0..719
    int ni   = rest / H_;           // 0..1
    int n    = chunk * 2 + ni;
    int c0   = cg * 16;

    unsigned int* r0 = g_S + (0 * 2 + ni) * CPW_ + (r + 1) * RS_;   // copy0 row
    unsigned int* r1 = g_S + (1 * 2 + ni) * CPW_ + (r + 1) * RS_;   // copy1 row

    uint4 a0 = *reinterpret_cast<uint4*>(r0 + c0);
    uint4 a1 = *reinterpret_cast<uint4*>(r0 + c0 + 4);
    uint4 a2 = *reinterpret_cast<uint4*>(r0 + c0 + 8);
    uint4 a3 = *reinterpret_cast<uint4*>(r0 + c0 + 12);

    uint4 b0 = *reinterpret_cast<uint4*>(r1 + c0);        // words c0..c0+3 (use .y.z.w)
    uint4 b1 = *reinterpret_cast<uint4*>(r1 + c0 + 4);
    uint4 b2 = *reinterpret_cast<uint4*>(r1 + c0 + 8);
    uint4 b3 = *reinterpret_cast<uint4*>(r1 + c0 + 12);
    unsigned int bt = r1[c0 + 16];                         // word c0+16 (cell c0+15)

    unsigned int av[16] = {a0.x,a0.y,a0.z,a0.w, a1.x,a1.y,a1.z,a1.w,
                           a2.x,a2.y,a2.z,a2.w, a3.x,a3.y,a3.z,a3.w};
    unsigned int bv[16] = {b0.y,b0.z,b0.w, b1.x,b1.y,b1.z,b1.w,
                           b2.x,b2.y,b2.z,b2.w, b3.x,b3.y,b3.z,b3.w, bt};

    float oimg[16], oone[16];
    #pragma unroll
    for (int j = 0; j < 16; j++) {
        float2 fa = unpack_h2(av[j]);
        float2 fb = unpack_h2(bv[j]);
        float den = fa.y + fb.y;
        oimg[j] = (fa.x + fb.x) / (den + EPS_);
        oone[j] = den;
    }

    int o = (n * H_ + r) * W_ + c0;
    float4* oi = reinterpret_cast<float4*>(out + o);
    float4* oo = reinterpret_cast<float4*>(out + S_ + o);
    #pragma unroll
    for (int j = 0; j < 4; j++) {
        oi[j] = make_float4(oimg[4*j], oimg[4*j+1], oimg[4*j+2], oimg[4*j+3]);
        oo[j] = make_float4(oone[4*j], oone[4*j+1], oone[4*j+2], oone[4*j+3]);
    }

    // zero-restore consumed words
    const uint4 z4 = make_uint4(0u, 0u, 0u, 0u);
    *reinterpret_cast<uint4*>(r0 + c0)      = z4;
    *reinterpret_cast<uint4*>(r0 + c0 + 4)  = z4;
    *reinterpret_cast<uint4*>(r0 + c0 + 8)  = z4;
    *reinterpret_cast<uint4*>(r0 + c0 + 12) = z4;
    r1[c0 + 1] = 0u;  r1[c0 + 2] = 0u;  r1[c0 + 3] = 0u;   // prologue words (word c0 = left neighbor's tail)
    *reinterpret_cast<uint4*>(r1 + c0 + 4)  = z4;
    *reinterpret_cast<uint4*>(r1 + c0 + 8)  = z4;
    *reinterpret_cast<uint4*>(r1 + c0 + 12) = z4;
    r1[c0 + 16] = 0u;                                       // tail word
}

extern "C" void kernel_launch(void* const* d_in, const int* in_sizes, int n_in,
                              void* d_out, int out_size)
{
    const float* img    = (const float*)d_in[0];
    const float* counts = (const float*)d_in[1];
    const float* flo    = (const float*)d_in[2];
    float* out = (float*)d_out;

    int splat_blocks = PC_ / 256;                    // 7200
    int norm_blocks  = (PC_ / 16) / 256;             // 450

    for (int chunk = 0; chunk < CHUNKS_; chunk++) {
        splat_kernel<<<splat_blocks, 256>>>(img, counts, flo, chunk);
        normalize_kernel<<<norm_blocks, 256>>>(out, chunk);
    }
}

// round 17
// speedup vs baseline: 1.2460x; 1.2460x over previous
#include <cuda_runtime.h>
#include <cuda_fp16.h>

// ForwardWarp: forward splatting with Gaussian softmax weights.
// img, counts: (8,1,720,1280) f32; flo: (8,2,720,1280) f32 (ch0 = y shifts W, ch1 = x shifts H)
// out: [0:S) = img_warp / (one_warp + eps), [S:2S) = one_warp
//
// R11 architecture (validated best, 102.9us), with CHUNKS=2 (pure scheduling change):
//  - Splat: one branchless red.global.add.noftz.v4.f16x2 per pixel into 4 parity copies
//    (pr=ix1&1, pc=iy1&1), rowpair-interleaved layout. ~1 add per f16 slot -> only fp16
//    packing error (~2.8e-4).
//  - Normalize: column-pair sweep, 4 pair-rows/segment; register-carries the straddling
//    pr=1 words (~1.0x read) and zero-restores exactly the consumed words (word-disjoint
//    -> race-free, no memset node).
//  - 2 chunks of 4 images share one 59.2MB scratch (fits 126MB L2; streamed inputs use
//    __ldcs). Fewer launch tails + deeper grids (splat 14400 blocks, normalize 900) at
//    UNCHANGED per-thread work.
// Measured dead-ends: fp32 payload, 2-copy scratch (RED op premium + latency-bound
// normalize), v2 pairs, 8x2/4x2 tiles, single-column, short segments, full 118MB scratch,
// __stcs outputs, fused overlap.

static constexpr int N_ = 8;
static constexpr int H_ = 720;
static constexpr int W_ = 1280;
static constexpr int S_ = N_ * H_ * W_;     // 7,372,800
static constexpr float EPS_ = 1e-6f;

static constexpr int CHUNKS_ = 2;           // 4 images per chunk
static constexpr int IPC_ = N_ / CHUNKS_;   // images per chunk = 4
static constexpr int PC_ = S_ / CHUNKS_;    // 3,686,400 pixels per chunk

static constexpr int NP_ = 361;             // pair-rows per copy per image (incl. pads)
static constexpr int WPAD_ = 2564;          // words per pair-row (16B multiple)
static constexpr int NPW_ = NP_ * WPAD_;    // words per copy per image
static constexpr int SCR_WORDS_ = 4 * IPC_ * NPW_;  // 4 copies x 4 images = 59.2MB

__device__ __align__(16) unsigned int g_S[SCR_WORDS_];  // BSS zero; fused zero-stores restore

__device__ __forceinline__ void red_v4h2(unsigned int* p, unsigned int s0, unsigned int s1,
                                         unsigned int s2, unsigned int s3) {
    asm volatile("red.global.add.noftz.v4.f16x2 [%0], {%1, %2, %3, %4};"
                 :: "l"(p), "r"(s0), "r"(s1), "r"(s2), "r"(s3) : "memory");
}
__device__ __forceinline__ unsigned int pack_h2(float a, float b) {
    __half2 h = __float22half2_rn(make_float2(a, b));
    return *reinterpret_cast<unsigned int*>(&h);
}
__device__ __forceinline__ float2 unpack_h2(unsigned int u) {
    return __half22float2(*reinterpret_cast<__half2*>(&u));
}

__global__ void __launch_bounds__(256) splat_kernel(
    const float* __restrict__ img,
    const float* __restrict__ counts,
    const float* __restrict__ flo,
    int chunk)
{
    int idx = chunk * PC_ + blockIdx.x * blockDim.x + threadIdx.x;

    int w  = idx % W_;
    int hw = idx / W_;
    int h  = hw % H_;
    int n  = hw / H_;
    int ni = n & (IPC_ - 1);        // image within chunk (0..3)

    int flo_base = ((n * 2) * H_ + h) * W_ + w;
    float y = __ldcs(flo + flo_base);
    float x = __ldcs(flo + flo_base + H_ * W_);

    float im = __ldcs(img + idx);
    float c  = __ldcs(counts + idx);

    float x1 = floorf(x);
    float y1 = floorf(y);
    float fx = x - x1;
    float fy = y - y1;
    float gx = fx - 1.0f;
    float gy = fy - 1.0f;

    float dx1 = fx * fx, dx2 = gx * gx;
    float dy1 = fy * fy, dy2 = gy * gy;

    float w11 = __expf(-(dx1 + dy1));   // row ix1, col iy1
    float w12 = __expf(-(dx1 + dy2));   // row ix1, col iy2
    float w21 = __expf(-(dx2 + dy1));   // row ix2, col iy1
    float w22 = __expf(-(dx2 + dy2));   // row ix2, col iy2
    float inv = 1.0f / (w11 + w12 + w21 + w22);
    float cinv = c * inv;

    int ix1 = (int)x1 + h;
    int iy1 = (int)y1 + w;

    if (ix1 < -1 || ix1 > H_ - 1 || iy1 < -1 || iy1 > W_ - 1) return;

    int pr = ix1 & 1;                     // (-1 & 1) == 1
    int pc = iy1 & 1;
    int P  = (ix1 + pr) >> 1;
    int wv = 2 * iy1 + 2 * pc;

    unsigned int* p = g_S + (((pr * 2 + pc) * IPC_ + ni) * NP_ + P) * WPAD_ + wv;

    // word order in footprint: [ (r1,c1), (r2,c1), (r1,c2), (r2,c2) ]
    red_v4h2(p,
             pack_h2(im * (w11 * cinv), w11 * cinv),
             pack_h2(im * (w21 * cinv), w21 * cinv),
             pack_h2(im * (w12 * cinv), w12 * cinv),
             pack_h2(im * (w22 * cinv), w22 * cinv));
}

// Column-sweep normalize (R11 per-thread shape). Thread owns cols {2y, 2y+1}, image ni,
// pair-rows [p0, p0+4). Step p finalizes output rows {2p, 2p+1}.
// Boundary pr=1 pairs shared with neighbor segments; each segment zero-stores ONLY the
// words it consumed (disjoint) -> race-free.
static constexpr int SEGS_ = 90;            // 360 pairs / 4 per segment

__global__ void __launch_bounds__(256) normalize_kernel(float* __restrict__ out, int chunk)
{
    int t = blockIdx.x * blockDim.x + threadIdx.x;  // 0 .. 230399 per chunk
    int y    = t % (W_ / 2);        // 0..639
    int rest = t / (W_ / 2);
    int seg  = rest % SEGS_;        // 0..89
    int ni   = rest / SEGS_;        // 0..3
    int n    = chunk * IPC_ + ni;
    int p0   = seg * 4;
    int q    = 4 * y;

    unsigned int* c00 = g_S + (0 * IPC_ + ni) * NPW_;
    unsigned int* c01 = g_S + (1 * IPC_ + ni) * NPW_;
    unsigned int* c10 = g_S + (2 * IPC_ + ni) * NPW_;
    unsigned int* c11 = g_S + (3 * IPC_ + ni) * NPW_;

    // prologue: carried pr=1 pair p0 (we consume only .y-side words of it)
    int rpro = p0 * WPAD_ + q;
    uint4 A  = *reinterpret_cast<uint4*>(c10 + rpro);
    uint2 E0 = *reinterpret_cast<uint2*>(c11 + rpro + 2);
    uint2 E1 = *reinterpret_cast<uint2*>(c11 + rpro + 4);

    const uint4 z4 = make_uint4(0u, 0u, 0u, 0u);
    const uint2 z2 = make_uint2(0u, 0u);

    #pragma unroll
    for (int i = 0; i < 4; i++) {
        int p   = p0 + i;
        int rp  = p * WPAD_ + q;
        int rp1 = rp + WPAD_;

        uint4 V  = *reinterpret_cast<uint4*>(c00 + rp);
        uint2 U0 = *reinterpret_cast<uint2*>(c01 + rp + 2);
        uint2 U1 = *reinterpret_cast<uint2*>(c01 + rp + 4);
        uint4 A2 = *reinterpret_cast<uint4*>(c10 + rp1);
        uint2 F0 = *reinterpret_cast<uint2*>(c11 + rp1 + 2);
        uint2 F1 = *reinterpret_cast<uint2*>(c11 + rp1 + 4);

        // row 2p:   c0 = V.x + U0.x + A.y + E0.y ;  c1 = V.z + U1.x + A.w + E1.y
        // row 2p+1: c0 = V.y + U0.y + A2.x + F0.x ; c1 = V.w + U1.y + A2.z + F1.x
        float2 a0 = unpack_h2(V.x),  a1 = unpack_h2(U0.x), a2 = unpack_h2(A.y),  a3 = unpack_h2(E0.y);
        float2 b0 = unpack_h2(V.z),  b1 = unpack_h2(U1.x), b2 = unpack_h2(A.w),  b3 = unpack_h2(E1.y);
        float2 d0 = unpack_h2(V.y),  d1 = unpack_h2(U0.y), d2 = unpack_h2(A2.x), d3 = unpack_h2(F0.x);
        float2 e0 = unpack_h2(V.w),  e1 = unpack_h2(U1.y), e2 = unpack_h2(A2.z), e3 = unpack_h2(F1.x);

        float numA = (a0.x + a1.x) + (a2.x + a3.x);
        float denA = (a0.y + a1.y) + (a2.y + a3.y);
        float numB = (b0.x + b1.x) + (b2.x + b3.x);
        float denB = (b0.y + b1.y) + (b2.y + b3.y);
        float numC = (d0.x + d1.x) + (d2.x + d3.x);
        float denC = (d0.y + d1.y) + (d2.y + d3.y);
        float numD = (e0.x + e1.x) + (e2.x + e3.x);
        float denD = (e0.y + e1.y) + (e2.y + e3.y);

        int o0 = ((n * H_) + 2 * p) * W_ + 2 * y;   // row 2p
        int o1 = o0 + W_;                            // row 2p+1
        *reinterpret_cast<float2*>(out + o0)      = make_float2(numA / (denA + EPS_), numB / (denB + EPS_));
        *reinterpret_cast<float2*>(out + o1)      = make_float2(numC / (denC + EPS_), numD / (denD + EPS_));
        *reinterpret_cast<float2*>(out + S_ + o0) = make_float2(denA, denB);
        *reinterpret_cast<float2*>(out + S_ + o1) = make_float2(denC, denD);

        // zero-restore pair p (c00/c01 fully owned by this step)
        *reinterpret_cast<uint4*>(c00 + rp)     = z4;
        *reinterpret_cast<uint2*>(c01 + rp + 2) = z2;
        *reinterpret_cast<uint2*>(c01 + rp + 4) = z2;
        if (i == 0) {
            // prologue pair: we consumed only the .y-side words
            c10[rp + 1] = 0u;  c10[rp + 3] = 0u;
            c11[rp + 3] = 0u;  c11[rp + 5] = 0u;
        } else {
            // interior pair: both word-sides consumed within this segment
            *reinterpret_cast<uint4*>(c10 + rp)     = z4;
            *reinterpret_cast<uint2*>(c11 + rp + 2) = z2;
            *reinterpret_cast<uint2*>(c11 + rp + 4) = z2;
        }

        A = A2; E0 = F0; E1 = F1;
    }

    // epilogue: pair p0+4 — we consumed only the .x-side words
    int re = (p0 + 4) * WPAD_ + q;
    c10[re]     = 0u;  c10[re + 2] = 0u;
    c11[re + 2] = 0u;  c11[re + 4] = 0u;
}

extern "C" void kernel_launch(void* const* d_in, const int* in_sizes, int n_in,
                              void* d_out, int out_size)
{
    const float* img    = (const float*)d_in[0];
    const float* counts = (const float*)d_in[1];
    const float* flo    = (const float*)d_in[2];
    float* out = (float*)d_out;

    int splat_blocks = PC_ / 256;                           // 14400
    int norm_blocks  = (W_ / 2) * SEGS_ * IPC_ / 256;       // 900

    for (int chunk = 0; chunk < CHUNKS_; chunk++) {
        splat_kernel<<<splat_blocks, 256>>>(img, counts, flo, chunk);
        normalize_kernel<<<norm_blocks, 256>>>(out, chunk);
    }
}